// round 3
// baseline (speedup 1.0000x reference)
#include <cuda_runtime.h>

#define Nn    6000
#define DEG   16
#define Mm    17          // DEG + 1
#define NT    16
#define MTt   10
#define NF    128
#define KT    160         // NT * MTt
#define PT    12          // padded per-template chunk (10 -> 12 for float4)
#define KTP   192         // NT * PT
#define NITER 10
#define THREADS 288       // 9 warps; 272 active update threads
#define GEMM_ROWS 40
#define GEMM_SMEM ((KT * 129 + GEMM_ROWS * NF) * 4)

// Scratch (no allocations allowed): G = x @ F2^T, plus squared norms
__device__ float g_G[Nn * KT];
__device__ float g_xn[Nn];
__device__ float g_f2n[KT];

// ---------------------------------------------------------------------------
// packed f32x2 helpers (sm_103a)
// ---------------------------------------------------------------------------
typedef unsigned long long ull;
__device__ __forceinline__ ull pk2(float lo, float hi) {
    ull r;
    asm("mov.b64 %0, {%1, %2};" : "=l"(r) : "f"(lo), "f"(hi));
    return r;
}
__device__ __forceinline__ void upk2(float& lo, float& hi, ull v) {
    asm("mov.b64 {%0, %1}, %2;" : "=f"(lo), "=f"(hi) : "l"(v));
}
__device__ __forceinline__ void ffma2(ull& d, ull a, ull b) {
    asm("fma.rn.f32x2 %0, %1, %2, %0;" : "+l"(d) : "l"(a), "l"(b));
}
__device__ __forceinline__ ull fma2r(ull a, ull b, ull c) {
    ull d;
    asm("fma.rn.f32x2 %0, %1, %2, %3;" : "=l"(d) : "l"(a), "l"(b), "l"(c));
    return d;
}
__device__ __forceinline__ void add2(ull& d, ull a) {
    asm("add.rn.f32x2 %0, %0, %1;" : "+l"(d) : "l"(a));
}
__device__ __forceinline__ void sub2(ull& d, ull a) {
    ull nz = a ^ 0x8000000080000000ULL;  // negate both lanes
    asm("add.rn.f32x2 %0, %0, %1;" : "+l"(d) : "l"(nz));
}
__device__ __forceinline__ float hadd2(ull v) {
    float lo, hi; upk2(lo, hi, v);
    return lo + hi;
}

// ---------------------------------------------------------------------------
// Kernel 1: G[n][kt] = sum_f x[n][f] * F2[kt][f]  (+ fused row norms)
// ---------------------------------------------------------------------------
__global__ __launch_bounds__(256, 2)
void gemm_kernel(const float* __restrict__ x, const float* __restrict__ F2) {
    extern __shared__ float sm[];
    float* sF2 = sm;                 // 160 x 129
    float* sX  = sm + KT * 129;      // 40 x 128
    int tid = threadIdx.x;
    int r0 = blockIdx.x * GEMM_ROWS;

    for (int i = tid; i < KT * NF; i += 256) {
        int r = i >> 7, f = i & 127;
        sF2[r * 129 + f] = F2[i];
    }
    for (int i = tid; i < GEMM_ROWS * NF; i += 256)
        sX[i] = x[(size_t)r0 * NF + i];
    __syncthreads();

    if (tid < GEMM_ROWS) {
        float s = 0.f;
        #pragma unroll 8
        for (int f = 0; f < NF; f++) { float v = sX[tid * NF + f]; s += v * v; }
        g_xn[r0 + tid] = s;
    }
    if (blockIdx.x == 0 && tid >= 64 && tid < 64 + KT) {
        int r = tid - 64;
        float s = 0.f;
        #pragma unroll 8
        for (int f = 0; f < NF; f++) { float v = sF2[r * 129 + f]; s += v * v; }
        g_f2n[r] = s;
    }

    int tm = tid >> 5;
    int tn = tid & 31;
    float acc[5][5];
    #pragma unroll
    for (int i = 0; i < 5; i++)
        #pragma unroll
        for (int j = 0; j < 5; j++) acc[i][j] = 0.f;

    for (int f = 0; f < NF; f++) {
        float av[5], bv[5];
        #pragma unroll
        for (int i = 0; i < 5; i++) av[i] = sX[(tm * 5 + i) * NF + f];
        #pragma unroll
        for (int j = 0; j < 5; j++) bv[j] = sF2[(tn * 5 + j) * 129 + f];
        #pragma unroll
        for (int i = 0; i < 5; i++)
            #pragma unroll
            for (int j = 0; j < 5; j++) acc[i][j] += av[i] * bv[j];
    }
    #pragma unroll
    for (int i = 0; i < 5; i++) {
        int row = r0 + tm * 5 + i;
        #pragma unroll
        for (int j = 0; j < 5; j++)
            g_G[(size_t)row * KT + tn * 5 + j] = acc[i][j];
    }
}

// ---------------------------------------------------------------------------
// Kernel 2: mirror-descent. One block/node, thread (k,m) owns 10-wide chunk.
// lt + McB live in registers (packed f32x2). Only T/q/cc/C2 are in smem.
// ---------------------------------------------------------------------------
struct SmemMain {
    float T   [Mm * KTP];          // 3264
    float C2  [NT * MTt * PT];     // 1920, rows padded to 12, pads zero
    float C2sq[NT * MTt * PT];     // 1920
    float q   [KTP];
    float cc  [KTP];
    float c1p[Mm];
    float xnl[Mm];
    int   nbrs[Mm];
    int   dstl[Mm * DEG];
    unsigned mask[Mm];
};

__global__ __launch_bounds__(THREADS, 4)
void main_kernel(const int* __restrict__ dst, const float* __restrict__ C2g,
                 const float* __restrict__ alpha0, float* __restrict__ out) {
    extern __shared__ char smraw[];
    SmemMain& s = *reinterpret_cast<SmemMain*>(smraw);
    int n = blockIdx.x, tid = threadIdx.x;

    float a0 = alpha0[0];
    float alpha = 1.f / (1.f + __expf(-a0));
    float coefA = alpha * 10.f;            // alpha / REG
    float coefM = (1.f - alpha) * 10.f;    // (1-alpha) / REG
    float cA2 = 2.f * coefA, cA4 = 4.f * coefA;
    ull cA2p = pk2(cA2, cA2);
    ull ncA4p = pk2(-cA4, -cA4);
    ull neg1p = pk2(-1.f, -1.f);

    // --- staging: nbrs, padded C2 / C2^2 ---
    if (tid < Mm) s.nbrs[tid] = (tid == 0) ? n : dst[n * DEG + tid - 1];
    for (int i = tid; i < NT * MTt * PT; i += THREADS) {
        int kt = i / PT, col = i - kt * PT;
        float v = (col < MTt) ? C2g[kt * MTt + col] : 0.f;
        s.C2[i] = v;
        s.C2sq[i] = v * v;
    }
    __syncthreads();
    if (tid < Mm * DEG)
        s.dstl[tid] = dst[s.nbrs[tid >> 4] * DEG + (tid & 15)];
    __syncthreads();

    // --- adjacency bitmask + c1p + xn ---
    if (tid < Mm) {
        int me = s.nbrs[tid];
        unsigned mrow = 0;
        for (int b = 0; b < Mm; b++) {
            int nb = s.nbrs[b];
            bool adj = false;
            #pragma unroll
            for (int j = 0; j < DEG; j++)
                adj = adj || (s.dstl[tid * DEG + j] == nb) ||
                             (s.dstl[b   * DEG + j] == me);
            if (adj) mrow |= (1u << b);
        }
        s.mask[tid] = mrow;
        s.c1p[tid]  = (float)__popc(mrow) * (1.f / (float)Mm);
        s.xnl[tid]  = g_xn[me];
    }
    __syncthreads();

    // --- per-thread persistent state ---
    const bool upd = tid < Mm * NT;        // 272 update threads
    int k = 0, m = 0;
    if (upd) { k = tid / Mm; m = tid - k * Mm; }
    const int tbase = k * PT;
    float* Trow = &s.T[m * KTP + tbase];
    unsigned msk_m = upd ? s.mask[m] : 0u;

    ull ltp[5], McBp[5];
    if (upd) {
        float xn = s.xnl[m];
        float cpv = cA2 * s.c1p[m];
        const float* Grow = g_G + (size_t)s.nbrs[m] * KT + k * MTt;
        const float* f2p  = g_f2n + k * MTt;
        #pragma unroll
        for (int j = 0; j < 5; j++) {
            float a = coefM * (xn + f2p[2*j]   - 2.f * Grow[2*j])   + cpv;
            float b = coefM * (xn + f2p[2*j+1] - 2.f * Grow[2*j+1]) + cpv;
            McBp[j] = pk2(a, b);
            ltp[j] = 0ULL;
        }
    }
    __syncthreads();

    // --- 10 mirror-descent iterations ---
    for (int it = 0; it < NITER; it++) {
        // A) softmax (registers) -> T
        if (upd) {
            float e[10];
            #pragma unroll
            for (int j = 0; j < 5; j++) upk2(e[2*j], e[2*j+1], ltp[j]);
            float mx = e[0];
            #pragma unroll
            for (int t = 1; t < MTt; t++) mx = fmaxf(mx, e[t]);
            float ssum = 0.f;
            #pragma unroll
            for (int t = 0; t < MTt; t++) { e[t] = __expf(e[t] - mx); ssum += e[t]; }
            float inv = (1.f / (float)Mm) / ssum;
            *(float4*)(Trow)     = make_float4(e[0]*inv, e[1]*inv, e[2]*inv, e[3]*inv);
            *(float4*)(Trow + 4) = make_float4(e[4]*inv, e[5]*inv, e[6]*inv, e[7]*inv);
            *(float4*)(Trow + 8) = make_float4(e[8]*inv, e[9]*inv, 0.f, 0.f);
        }
        __syncthreads();

        // W1) q (48 thr) || gather Y1 into regs (m != 0)
        ull y1p[5];
        if (tid < 48) {
            int kk = tid / 3, j4 = (tid - kk * 3) * 4;
            int off = kk * PT + j4;
            float4 acc = make_float4(0.f, 0.f, 0.f, 0.f);
            #pragma unroll
            for (int mm = 0; mm < Mm; mm++) {
                float4 t = *(const float4*)&s.T[mm * KTP + off];
                acc.x += t.x; acc.y += t.y; acc.z += t.z; acc.w += t.w;
            }
            *(float4*)&s.q[off] = acc;
        }
        #pragma unroll
        for (int j = 0; j < 5; j++) y1p[j] = 0ULL;
        if (upd && m != 0) {
            unsigned msk = msk_m;
            while (msk) {
                int b = __ffs(msk) - 1;
                msk &= msk - 1;
                const float* tr = &s.T[b * KTP + tbase];
                float4 v0 = *(const float4*)(tr);
                float4 v1 = *(const float4*)(tr + 4);
                float4 v2 = *(const float4*)(tr + 8);
                add2(y1p[0], pk2(v0.x, v0.y));
                add2(y1p[1], pk2(v0.z, v0.w));
                add2(y1p[2], pk2(v1.x, v1.y));
                add2(y1p[3], pk2(v1.z, v1.w));
                add2(y1p[4], pk2(v2.x, v2.y));
            }
        }
        __syncthreads();

        // W2) cc (160 thr)  ||  m==0 Y1 from q  ||  y2 dots (all upd threads)
        if (tid < KT) {
            int c = tid, kk = c / MTt, ss = c - kk * MTt;
            const float* qp = &s.q[kk * PT];
            const float* sq = &s.C2sq[(kk * MTt + ss) * PT];
            float4 q0 = *(const float4*)(qp), q1 = *(const float4*)(qp + 4),
                   q2 = *(const float4*)(qp + 8);
            float4 s0 = *(const float4*)(sq), s1 = *(const float4*)(sq + 4),
                   s2 = *(const float4*)(sq + 8);
            ull acc = 0ULL;
            ffma2(acc, pk2(q0.x, q0.y), pk2(s0.x, s0.y));
            ffma2(acc, pk2(q0.z, q0.w), pk2(s0.z, s0.w));
            ffma2(acc, pk2(q1.x, q1.y), pk2(s1.x, s1.y));
            ffma2(acc, pk2(q1.z, q1.w), pk2(s1.z, s1.w));
            ffma2(acc, pk2(q2.x, q2.y), pk2(s2.x, s2.y));
            s.cc[kk * PT + ss] = hadd2(acc);
        }
        ull acc[5];
        #pragma unroll
        for (int j = 0; j < 5; j++) acc[j] = 0ULL;
        if (upd) {
            if (m == 0) {
                const float* qp = &s.q[tbase];
                float4 q0 = *(const float4*)(qp), q1 = *(const float4*)(qp + 4),
                       q2 = *(const float4*)(qp + 8);
                y1p[0] = pk2(q0.x, q0.y); y1p[1] = pk2(q0.z, q0.w);
                y1p[2] = pk2(q1.x, q1.y); y1p[3] = pk2(q1.z, q1.w);
                y1p[4] = pk2(q2.x, q2.y);
                if (!(msk_m & 1u)) {   // diagonal absent: remove T[0]
                    const float* tr = &s.T[tbase];  // row 0
                    float4 v0 = *(const float4*)(tr), v1 = *(const float4*)(tr + 4),
                           v2 = *(const float4*)(tr + 8);
                    sub2(y1p[0], pk2(v0.x, v0.y));
                    sub2(y1p[1], pk2(v0.z, v0.w));
                    sub2(y1p[2], pk2(v1.x, v1.y));
                    sub2(y1p[3], pk2(v1.z, v1.w));
                    sub2(y1p[4], pk2(v2.x, v2.y));
                }
            }
            float y[10];
            #pragma unroll
            for (int j = 0; j < 5; j++) upk2(y[2*j], y[2*j+1], y1p[j]);
            // y2[s] = sum_t y[t] * C2[k][t][s]   (C2 symmetric)
            #pragma unroll
            for (int t = 0; t < MTt; t++) {
                const float* cr = &s.C2[(k * MTt + t) * PT];
                float4 r0 = *(const float4*)(cr), r1 = *(const float4*)(cr + 4),
                       r2 = *(const float4*)(cr + 8);
                ull yt = pk2(y[t], y[t]);
                ffma2(acc[0], yt, pk2(r0.x, r0.y));
                ffma2(acc[1], yt, pk2(r0.z, r0.w));
                ffma2(acc[2], yt, pk2(r1.x, r1.y));
                ffma2(acc[3], yt, pk2(r1.z, r1.w));
                ffma2(acc[4], yt, pk2(r2.x, r2.y));
            }
        }
        __syncthreads();

        // lt update (registers + cc read)
        if (upd) {
            const float* cp = &s.cc[tbase];
            float4 c0 = *(const float4*)(cp), c1 = *(const float4*)(cp + 4),
                   c2v = *(const float4*)(cp + 8);
            ull ccp[5] = { pk2(c0.x, c0.y), pk2(c0.z, c0.w),
                           pk2(c1.x, c1.y), pk2(c1.z, c1.w),
                           pk2(c2v.x, c2v.y) };
            #pragma unroll
            for (int j = 0; j < 5; j++) {
                ull d = fma2r(cA2p, ccp[j], McBp[j]);   // McB + 2cA*cc
                d = fma2r(ncA4p, acc[j], d);            // - 4cA*y2
                ltp[j] = fma2r(d, neg1p, ltp[j]);       // lt -= d
            }
        }
        __syncthreads();
    }

    // --- final T and marginal q -> output ---
    if (upd) {
        float e[10];
        #pragma unroll
        for (int j = 0; j < 5; j++) upk2(e[2*j], e[2*j+1], ltp[j]);
        float mx = e[0];
        #pragma unroll
        for (int t = 1; t < MTt; t++) mx = fmaxf(mx, e[t]);
        float ssum = 0.f;
        #pragma unroll
        for (int t = 0; t < MTt; t++) { e[t] = __expf(e[t] - mx); ssum += e[t]; }
        float inv = (1.f / (float)Mm) / ssum;
        *(float4*)(Trow)     = make_float4(e[0]*inv, e[1]*inv, e[2]*inv, e[3]*inv);
        *(float4*)(Trow + 4) = make_float4(e[4]*inv, e[5]*inv, e[6]*inv, e[7]*inv);
        *(float4*)(Trow + 8) = make_float4(e[8]*inv, e[9]*inv, 0.f, 0.f);
    }
    __syncthreads();
    if (tid < KT) {
        int ck = tid / MTt, cs = tid - ck * MTt;
        int c12 = ck * PT + cs;
        float sq = 0.f;
        #pragma unroll
        for (int mm = 0; mm < Mm; mm++) sq += s.T[mm * KTP + c12];
        out[(size_t)n * KT + tid] = sq;
    }
}

// ---------------------------------------------------------------------------
extern "C" void kernel_launch(void* const* d_in, const int* in_sizes, int n_in,
                              void* d_out, int out_size) {
    const float* x   = (const float*)d_in[0];
    const int*   ei  = (const int*)d_in[1];
    const float* C2g = (const float*)d_in[2];
    const float* F2  = (const float*)d_in[3];
    const float* a0  = (const float*)d_in[4];
    float* out = (float*)d_out;
    const int* dst = ei + Nn * DEG;

    cudaFuncSetAttribute(gemm_kernel, cudaFuncAttributeMaxDynamicSharedMemorySize,
                         GEMM_SMEM);
    cudaFuncSetAttribute(main_kernel, cudaFuncAttributeMaxDynamicSharedMemorySize,
                         (int)sizeof(SmemMain));

    gemm_kernel<<<Nn / GEMM_ROWS, 256, GEMM_SMEM>>>(x, F2);
    main_kernel<<<Nn, THREADS, sizeof(SmemMain)>>>(dst, C2g, a0, out);
}

// round 5
// speedup vs baseline: 1.1283x; 1.1283x over previous
#include <cuda_runtime.h>

#define Nn    6000
#define DEG   16
#define Mm    17          // DEG + 1
#define NT    16
#define MTt   10
#define NF    128
#define KT    160         // NT * MTt
#define PT    12          // padded per-template chunk (10 -> 12 for float4)
#define KTP   192         // NT * PT (column layout for q/cc/out)
#define TSTR  196         // T row stride: 196 mod 32 = 4  -> <=3-way conflicts
#define NITER 10
#define THREADS 288       // 9 warps; 272 active update threads
#define GEMM_ROWS 40
#define GEMM_SMEM ((KT * 129 + GEMM_ROWS * NF) * 4)

// Scratch (no allocations allowed): G = x @ F2^T, plus squared norms
__device__ float g_G[Nn * KT];
__device__ float g_xn[Nn];
__device__ float g_f2n[KT];

// ---------------------------------------------------------------------------
// packed f32x2 helpers (sm_103a)
// ---------------------------------------------------------------------------
typedef unsigned long long ull;
__device__ __forceinline__ ull pk2(float lo, float hi) {
    ull r;
    asm("mov.b64 %0, {%1, %2};" : "=l"(r) : "f"(lo), "f"(hi));
    return r;
}
__device__ __forceinline__ void upk2(float& lo, float& hi, ull v) {
    asm("mov.b64 {%0, %1}, %2;" : "=f"(lo), "=f"(hi) : "l"(v));
}
__device__ __forceinline__ void ffma2(ull& d, ull a, ull b) {
    asm("fma.rn.f32x2 %0, %1, %2, %0;" : "+l"(d) : "l"(a), "l"(b));
}
__device__ __forceinline__ ull fma2r(ull a, ull b, ull c) {
    ull d;
    asm("fma.rn.f32x2 %0, %1, %2, %3;" : "=l"(d) : "l"(a), "l"(b), "l"(c));
    return d;
}
__device__ __forceinline__ void add2(ull& d, ull a) {
    asm("add.rn.f32x2 %0, %0, %1;" : "+l"(d) : "l"(a));
}
__device__ __forceinline__ void sub2(ull& d, ull a) {
    ull nz = a ^ 0x8000000080000000ULL;  // negate both lanes
    asm("add.rn.f32x2 %0, %0, %1;" : "+l"(d) : "l"(nz));
}
__device__ __forceinline__ float hadd2(ull v) {
    float lo, hi; upk2(lo, hi, v);
    return lo + hi;
}

// ---------------------------------------------------------------------------
// Kernel 1: G[n][kt] = sum_f x[n][f] * F2[kt][f]  (+ fused row norms)
// ---------------------------------------------------------------------------
__global__ __launch_bounds__(256, 2)
void gemm_kernel(const float* __restrict__ x, const float* __restrict__ F2) {
    extern __shared__ float sm[];
    float* sF2 = sm;                 // 160 x 129
    float* sX  = sm + KT * 129;      // 40 x 128
    int tid = threadIdx.x;
    int r0 = blockIdx.x * GEMM_ROWS;

    for (int i = tid; i < KT * NF; i += 256) {
        int r = i >> 7, f = i & 127;
        sF2[r * 129 + f] = F2[i];
    }
    for (int i = tid; i < GEMM_ROWS * NF; i += 256)
        sX[i] = x[(size_t)r0 * NF + i];
    __syncthreads();

    if (tid < GEMM_ROWS) {
        float s = 0.f;
        #pragma unroll 8
        for (int f = 0; f < NF; f++) { float v = sX[tid * NF + f]; s += v * v; }
        g_xn[r0 + tid] = s;
    }
    if (blockIdx.x == 0 && tid >= 64 && tid < 64 + KT) {
        int r = tid - 64;
        float s = 0.f;
        #pragma unroll 8
        for (int f = 0; f < NF; f++) { float v = sF2[r * 129 + f]; s += v * v; }
        g_f2n[r] = s;
    }

    int tm = tid >> 5;
    int tn = tid & 31;
    float acc[5][5];
    #pragma unroll
    for (int i = 0; i < 5; i++)
        #pragma unroll
        for (int j = 0; j < 5; j++) acc[i][j] = 0.f;

    for (int f = 0; f < NF; f++) {
        float av[5], bv[5];
        #pragma unroll
        for (int i = 0; i < 5; i++) av[i] = sX[(tm * 5 + i) * NF + f];
        #pragma unroll
        for (int j = 0; j < 5; j++) bv[j] = sF2[(tn * 5 + j) * 129 + f];
        #pragma unroll
        for (int i = 0; i < 5; i++)
            #pragma unroll
            for (int j = 0; j < 5; j++) acc[i][j] += av[i] * bv[j];
    }
    #pragma unroll
    for (int i = 0; i < 5; i++) {
        int row = r0 + tm * 5 + i;
        #pragma unroll
        for (int j = 0; j < 5; j++)
            g_G[(size_t)row * KT + tn * 5 + j] = acc[i][j];
    }
}

// ---------------------------------------------------------------------------
// Kernel 2: mirror-descent. One block/node, thread (k,m) owns 10-wide chunk.
// lt + McB live in registers (packed f32x2). T rows padded to stride 196.
// ---------------------------------------------------------------------------
struct SmemMain {
    float T   [Mm * TSTR];         // rows stride 196 (bank-decorrelated)
    float C2  [NT * MTt * PT];     // 1920, rows padded to 12, pads zero
    float C2sq[NT * MTt * PT];     // 1920
    float q   [KTP];
    float cc  [KTP];
    float c1p[Mm];
    float xnl[Mm];
    int   nbrs[Mm];
    int   dstl[Mm * DEG];
    unsigned mask[Mm];
};

__global__ __launch_bounds__(THREADS, 4)
void main_kernel(const int* __restrict__ dst, const float* __restrict__ C2g,
                 const float* __restrict__ alpha0, float* __restrict__ out) {
    extern __shared__ char smraw[];
    SmemMain& s = *reinterpret_cast<SmemMain*>(smraw);
    int n = blockIdx.x, tid = threadIdx.x;

    float a0 = alpha0[0];
    float alpha = 1.f / (1.f + __expf(-a0));
    float coefA = alpha * 10.f;            // alpha / REG
    float coefM = (1.f - alpha) * 10.f;    // (1-alpha) / REG
    float cA2 = 2.f * coefA, cA4 = 4.f * coefA;
    ull cA2p = pk2(cA2, cA2);
    ull ncA4p = pk2(-cA4, -cA4);
    ull neg1p = pk2(-1.f, -1.f);

    // --- staging: nbrs, padded C2 / C2^2 ---
    if (tid < Mm) s.nbrs[tid] = (tid == 0) ? n : dst[n * DEG + tid - 1];
    for (int i = tid; i < NT * MTt * PT; i += THREADS) {
        int kt = i / PT, col = i - kt * PT;
        float v = (col < MTt) ? C2g[kt * MTt + col] : 0.f;
        s.C2[i] = v;
        s.C2sq[i] = v * v;
    }
    __syncthreads();
    if (tid < Mm * DEG)
        s.dstl[tid] = dst[s.nbrs[tid >> 4] * DEG + (tid & 15)];
    __syncthreads();

    // --- adjacency bitmask + c1p + xn ---
    if (tid < Mm) {
        int me = s.nbrs[tid];
        unsigned mrow = 0;
        for (int b = 0; b < Mm; b++) {
            int nb = s.nbrs[b];
            bool adj = false;
            #pragma unroll
            for (int j = 0; j < DEG; j++)
                adj = adj || (s.dstl[tid * DEG + j] == nb) ||
                             (s.dstl[b   * DEG + j] == me);
            if (adj) mrow |= (1u << b);
        }
        s.mask[tid] = mrow;
        s.c1p[tid]  = (float)__popc(mrow) * (1.f / (float)Mm);
        s.xnl[tid]  = g_xn[me];
    }
    __syncthreads();

    // --- per-thread persistent state ---
    const bool upd = tid < Mm * NT;        // 272 update threads
    int k = 0, m = 0;
    if (upd) { k = tid / Mm; m = tid - k * Mm; }
    const int tbase = k * PT;
    float* Trow = &s.T[m * TSTR + tbase];
    unsigned msk_m = upd ? s.mask[m] : 0u;

    ull ltp[5], McBp[5];
    if (upd) {
        float xn = s.xnl[m];
        float cpv = cA2 * s.c1p[m];
        const float* Grow = g_G + (size_t)s.nbrs[m] * KT + k * MTt;
        const float* f2p  = g_f2n + k * MTt;
        #pragma unroll
        for (int j = 0; j < 5; j++) {
            float a = coefM * (xn + f2p[2*j]   - 2.f * Grow[2*j])   + cpv;
            float b = coefM * (xn + f2p[2*j+1] - 2.f * Grow[2*j+1]) + cpv;
            McBp[j] = pk2(a, b);
            ltp[j] = 0ULL;
        }
    }
    __syncthreads();

    // --- 10 mirror-descent iterations (3 syncs each) ---
    ull ccp[5];       // cc carried from previous W2 stage
    ull y2p[5];       // y2 carried from previous W2 stage
    #pragma unroll
    for (int j = 0; j < 5; j++) { ccp[j] = 0ULL; y2p[j] = 0ULL; }

    for (int it = 0; it < NITER; it++) {
        // A) lt register update (skipped on it==0) + softmax -> T
        if (upd) {
            if (it > 0) {
                #pragma unroll
                for (int j = 0; j < 5; j++) {
                    ull d = fma2r(cA2p, ccp[j], McBp[j]);   // McB + 2cA*cc
                    d = fma2r(ncA4p, y2p[j], d);            // - 4cA*y2
                    ltp[j] = fma2r(d, neg1p, ltp[j]);       // lt -= d
                }
            }
            float e[10];
            #pragma unroll
            for (int j = 0; j < 5; j++) upk2(e[2*j], e[2*j+1], ltp[j]);
            float mx = e[0];
            #pragma unroll
            for (int t = 1; t < MTt; t++) mx = fmaxf(mx, e[t]);
            float ssum = 0.f;
            #pragma unroll
            for (int t = 0; t < MTt; t++) { e[t] = __expf(e[t] - mx); ssum += e[t]; }
            float inv = (1.f / (float)Mm) / ssum;
            *(float4*)(Trow)     = make_float4(e[0]*inv, e[1]*inv, e[2]*inv, e[3]*inv);
            *(float4*)(Trow + 4) = make_float4(e[4]*inv, e[5]*inv, e[6]*inv, e[7]*inv);
            *(float4*)(Trow + 8) = make_float4(e[8]*inv, e[9]*inv, 0.f, 0.f);
        }
        __syncthreads();

        // W1) q (48 thr) || sparse gather Y1 into regs (m != 0)
        ull y1p[5];
        if (tid < 48) {
            int kk = tid / 3, j4 = (tid - kk * 3) * 4;
            float4 acc = make_float4(0.f, 0.f, 0.f, 0.f);
            #pragma unroll
            for (int mm = 0; mm < Mm; mm++) {
                float4 t = *(const float4*)&s.T[mm * TSTR + kk * PT + j4];
                acc.x += t.x; acc.y += t.y; acc.z += t.z; acc.w += t.w;
            }
            *(float4*)&s.q[kk * PT + j4] = acc;
        }
        #pragma unroll
        for (int j = 0; j < 5; j++) y1p[j] = 0ULL;
        if (upd && m != 0) {
            unsigned msk = msk_m;
            while (msk) {
                int b = __ffs(msk) - 1;
                msk &= msk - 1;
                const float* tr = &s.T[b * TSTR + tbase];
                float4 v0 = *(const float4*)(tr);
                float4 v1 = *(const float4*)(tr + 4);
                float4 v2 = *(const float4*)(tr + 8);
                add2(y1p[0], pk2(v0.x, v0.y));
                add2(y1p[1], pk2(v0.z, v0.w));
                add2(y1p[2], pk2(v1.x, v1.y));
                add2(y1p[3], pk2(v1.z, v1.w));
                add2(y1p[4], pk2(v2.x, v2.y));
            }
        }
        __syncthreads();

        // W2) cc (160 thr)  ||  m==0 Y1 from q  ||  y2 dots (all upd threads)
        if (tid < KT) {
            int kk = tid / MTt, ss = tid - kk * MTt;
            const float* qp = &s.q[kk * PT];
            const float* sq = &s.C2sq[(kk * MTt + ss) * PT];
            float4 q0 = *(const float4*)(qp), q1 = *(const float4*)(qp + 4),
                   q2 = *(const float4*)(qp + 8);
            float4 s0 = *(const float4*)(sq), s1 = *(const float4*)(sq + 4),
                   s2 = *(const float4*)(sq + 8);
            ull acc = 0ULL;
            ffma2(acc, pk2(q0.x, q0.y), pk2(s0.x, s0.y));
            ffma2(acc, pk2(q0.z, q0.w), pk2(s0.z, s0.w));
            ffma2(acc, pk2(q1.x, q1.y), pk2(s1.x, s1.y));
            ffma2(acc, pk2(q1.z, q1.w), pk2(s1.z, s1.w));
            ffma2(acc, pk2(q2.x, q2.y), pk2(s2.x, s2.y));
            s.cc[kk * PT + ss] = hadd2(acc);
        }
        if (upd) {
            if (m == 0) {
                const float* qp = &s.q[tbase];
                float4 q0 = *(const float4*)(qp), q1 = *(const float4*)(qp + 4),
                       q2 = *(const float4*)(qp + 8);
                y1p[0] = pk2(q0.x, q0.y); y1p[1] = pk2(q0.z, q0.w);
                y1p[2] = pk2(q1.x, q1.y); y1p[3] = pk2(q1.z, q1.w);
                y1p[4] = pk2(q2.x, q2.y);
                if (!(msk_m & 1u)) {   // diagonal absent: remove T[0]
                    const float* tr = &s.T[tbase];  // row 0
                    float4 v0 = *(const float4*)(tr), v1 = *(const float4*)(tr + 4),
                           v2 = *(const float4*)(tr + 8);
                    sub2(y1p[0], pk2(v0.x, v0.y));
                    sub2(y1p[1], pk2(v0.z, v0.w));
                    sub2(y1p[2], pk2(v1.x, v1.y));
                    sub2(y1p[3], pk2(v1.z, v1.w));
                    sub2(y1p[4], pk2(v2.x, v2.y));
                }
            }
            float y[10];
            #pragma unroll
            for (int j = 0; j < 5; j++) upk2(y[2*j], y[2*j+1], y1p[j]);
            #pragma unroll
            for (int j = 0; j < 5; j++) y2p[j] = 0ULL;
            // y2[s] = sum_t y[t] * C2[k][t][s]   (C2 symmetric)
            #pragma unroll
            for (int t = 0; t < MTt; t++) {
                const float* cr = &s.C2[(k * MTt + t) * PT];
                float4 r0 = *(const float4*)(cr), r1 = *(const float4*)(cr + 4),
                       r2 = *(const float4*)(cr + 8);
                ull yt = pk2(y[t], y[t]);
                ffma2(y2p[0], yt, pk2(r0.x, r0.y));
                ffma2(y2p[1], yt, pk2(r0.z, r0.w));
                ffma2(y2p[2], yt, pk2(r1.x, r1.y));
                ffma2(y2p[3], yt, pk2(r1.z, r1.w));
                ffma2(y2p[4], yt, pk2(r2.x, r2.y));
            }
        }
        __syncthreads();

        // read cc into registers for the deferred update
        if (upd) {
            const float* cp = &s.cc[tbase];
            float4 c0 = *(const float4*)(cp), c1 = *(const float4*)(cp + 4),
                   c2v = *(const float4*)(cp + 8);
            ccp[0] = pk2(c0.x, c0.y); ccp[1] = pk2(c0.z, c0.w);
            ccp[2] = pk2(c1.x, c1.y); ccp[3] = pk2(c1.z, c1.w);
            ccp[4] = pk2(c2v.x, c2v.y);
        }
    }

    // --- final lt update + T and marginal q -> output ---
    if (upd) {
        #pragma unroll
        for (int j = 0; j < 5; j++) {
            ull d = fma2r(cA2p, ccp[j], McBp[j]);
            d = fma2r(ncA4p, y2p[j], d);
            ltp[j] = fma2r(d, neg1p, ltp[j]);
        }
        float e[10];
        #pragma unroll
        for (int j = 0; j < 5; j++) upk2(e[2*j], e[2*j+1], ltp[j]);
        float mx = e[0];
        #pragma unroll
        for (int t = 1; t < MTt; t++) mx = fmaxf(mx, e[t]);
        float ssum = 0.f;
        #pragma unroll
        for (int t = 0; t < MTt; t++) { e[t] = __expf(e[t] - mx); ssum += e[t]; }
        float inv = (1.f / (float)Mm) / ssum;
        *(float4*)(Trow)     = make_float4(e[0]*inv, e[1]*inv, e[2]*inv, e[3]*inv);
        *(float4*)(Trow + 4) = make_float4(e[4]*inv, e[5]*inv, e[6]*inv, e[7]*inv);
        *(float4*)(Trow + 8) = make_float4(e[8]*inv, e[9]*inv, 0.f, 0.f);
    }
    __syncthreads();
    if (tid < KT) {
        int ck = tid / MTt, cs = tid - ck * MTt;
        float sq = 0.f;
        #pragma unroll
        for (int mm = 0; mm < Mm; mm++) sq += s.T[mm * TSTR + ck * PT + cs];
        out[(size_t)n * KT + tid] = sq;
    }
}

// ---------------------------------------------------------------------------
extern "C" void kernel_launch(void* const* d_in, const int* in_sizes, int n_in,
                              void* d_out, int out_size) {
    const float* x   = (const float*)d_in[0];
    const int*   ei  = (const int*)d_in[1];
    const float* C2g = (const float*)d_in[2];
    const float* F2  = (const float*)d_in[3];
    const float* a0  = (const float*)d_in[4];
    float* out = (float*)d_out;
    const int* dst = ei + Nn * DEG;

    cudaFuncSetAttribute(gemm_kernel, cudaFuncAttributeMaxDynamicSharedMemorySize,
                         GEMM_SMEM);
    cudaFuncSetAttribute(main_kernel, cudaFuncAttributeMaxDynamicSharedMemorySize,
                         (int)sizeof(SmemMain));

    gemm_kernel<<<Nn / GEMM_ROWS, 256, GEMM_SMEM>>>(x, F2);
    main_kernel<<<Nn, THREADS, sizeof(SmemMain)>>>(dst, C2g, a0, out);
}

// round 6
// speedup vs baseline: 1.1595x; 1.0277x over previous
#include <cuda_runtime.h>

#define Nn    6000
#define DEG   16
#define Mm    17          // DEG + 1
#define NT    16
#define MTt   10
#define NF    128
#define KT    160         // NT * MTt
#define PT    12          // padded per-template chunk (10 -> 12 for float4)
#define KTP   192         // NT * PT
#define TSTR  196         // T row stride (words); 196 mod 32 = 4
#define NITER 10
#define THREADS 288       // 9 warps
#define GEMM_ROWS 40
#define GEMM_SMEM ((KT * 129 + GEMM_ROWS * NF) * 4)

__device__ float g_G[Nn * KT];
__device__ float g_xn[Nn];
__device__ float g_f2n[KT];

// ---------------------------------------------------------------------------
// packed f32x2 helpers (sm_103a)
// ---------------------------------------------------------------------------
typedef unsigned long long ull;
__device__ __forceinline__ ull pk2(float lo, float hi) {
    ull r;
    asm("mov.b64 %0, {%1, %2};" : "=l"(r) : "f"(lo), "f"(hi));
    return r;
}
__device__ __forceinline__ void upk2(float& lo, float& hi, ull v) {
    asm("mov.b64 {%0, %1}, %2;" : "=f"(lo), "=f"(hi) : "l"(v));
}
__device__ __forceinline__ void ffma2(ull& d, ull a, ull b) {
    asm("fma.rn.f32x2 %0, %1, %2, %0;" : "+l"(d) : "l"(a), "l"(b));
}
__device__ __forceinline__ ull fma2r(ull a, ull b, ull c) {
    ull d;
    asm("fma.rn.f32x2 %0, %1, %2, %3;" : "=l"(d) : "l"(a), "l"(b), "l"(c));
    return d;
}
__device__ __forceinline__ void add2(ull& d, ull a) {
    asm("add.rn.f32x2 %0, %0, %1;" : "+l"(d) : "l"(a));
}
__device__ __forceinline__ void sub2(ull& d, ull a) {
    ull nz = a ^ 0x8000000080000000ULL;
    asm("add.rn.f32x2 %0, %0, %1;" : "+l"(d) : "l"(nz));
}
__device__ __forceinline__ float hadd2(ull v) {
    float lo, hi; upk2(lo, hi, v);
    return lo + hi;
}

// ---------------------------------------------------------------------------
// Kernel 1: G = x @ F2^T (+ fused row norms)
// ---------------------------------------------------------------------------
__global__ __launch_bounds__(256, 2)
void gemm_kernel(const float* __restrict__ x, const float* __restrict__ F2) {
    extern __shared__ float sm[];
    float* sF2 = sm;                 // 160 x 129
    float* sX  = sm + KT * 129;      // 40 x 128
    int tid = threadIdx.x;
    int r0 = blockIdx.x * GEMM_ROWS;

    for (int i = tid; i < KT * NF; i += 256) {
        int r = i >> 7, f = i & 127;
        sF2[r * 129 + f] = F2[i];
    }
    for (int i = tid; i < GEMM_ROWS * NF; i += 256)
        sX[i] = x[(size_t)r0 * NF + i];
    __syncthreads();

    if (tid < GEMM_ROWS) {
        float s = 0.f;
        #pragma unroll 8
        for (int f = 0; f < NF; f++) { float v = sX[tid * NF + f]; s += v * v; }
        g_xn[r0 + tid] = s;
    }
    if (blockIdx.x == 0 && tid >= 64 && tid < 64 + KT) {
        int r = tid - 64;
        float s = 0.f;
        #pragma unroll 8
        for (int f = 0; f < NF; f++) { float v = sF2[r * 129 + f]; s += v * v; }
        g_f2n[r] = s;
    }

    int tm = tid >> 5;
    int tn = tid & 31;
    float acc[5][5];
    #pragma unroll
    for (int i = 0; i < 5; i++)
        #pragma unroll
        for (int j = 0; j < 5; j++) acc[i][j] = 0.f;

    for (int f = 0; f < NF; f++) {
        float av[5], bv[5];
        #pragma unroll
        for (int i = 0; i < 5; i++) av[i] = sX[(tm * 5 + i) * NF + f];
        #pragma unroll
        for (int j = 0; j < 5; j++) bv[j] = sF2[(tn * 5 + j) * 129 + f];
        #pragma unroll
        for (int i = 0; i < 5; i++)
            #pragma unroll
            for (int j = 0; j < 5; j++) acc[i][j] += av[i] * bv[j];
    }
    #pragma unroll
    for (int i = 0; i < 5; i++) {
        int row = r0 + tm * 5 + i;
        #pragma unroll
        for (int j = 0; j < 5; j++)
            g_G[(size_t)row * KT + tn * 5 + j] = acc[i][j];
    }
}

// ---------------------------------------------------------------------------
// Kernel 2: warp-aligned mirror-descent.
//  warps 0-7: lane = [k-half(1b)][m-1(4b)], k = 2*warp + half, m = 1..16
//  warp 8, lanes 0-15: row m=0 for k = lane
// ---------------------------------------------------------------------------
struct SmemMain {
    float T   [Mm * TSTR];
    float C2  [NT * MTt * PT];     // rows padded to 12, pads zero
    float C2sq[NT * MTt * PT];
    float q   [KTP];
    float cc  [KTP];
    float c1p[Mm];
    float xnl[Mm];
    int   nbrs[Mm];
    int   dstl[Mm * DEG];
    unsigned mask[Mm];
};

__global__ __launch_bounds__(THREADS, 4)
void main_kernel(const int* __restrict__ dst, const float* __restrict__ C2g,
                 const float* __restrict__ alpha0, float* __restrict__ out) {
    extern __shared__ char smraw[];
    SmemMain& s = *reinterpret_cast<SmemMain*>(smraw);
    int n = blockIdx.x, tid = threadIdx.x;
    int w = tid >> 5, lane = tid & 31;

    float a0 = alpha0[0];
    float alpha = 1.f / (1.f + __expf(-a0));
    float coefA = alpha * 10.f;            // alpha / REG
    float coefM = (1.f - alpha) * 10.f;    // (1-alpha) / REG
    float cA2 = 2.f * coefA, cA4 = 4.f * coefA;
    ull cA2p = pk2(cA2, cA2);
    ull ncA4p = pk2(-cA4, -cA4);
    ull neg1p = pk2(-1.f, -1.f);

    // --- staging ---
    if (tid < Mm) s.nbrs[tid] = (tid == 0) ? n : dst[n * DEG + tid - 1];
    for (int i = tid; i < NT * MTt * PT; i += THREADS) {
        int kt = i / PT, col = i - kt * PT;
        float v = (col < MTt) ? C2g[kt * MTt + col] : 0.f;
        s.C2[i] = v;
        s.C2sq[i] = v * v;
    }
    for (int i = tid; i < KTP; i += THREADS) s.q[i] = 0.f;
    __syncthreads();
    if (tid < Mm * DEG)
        s.dstl[tid] = dst[s.nbrs[tid >> 4] * DEG + (tid & 15)];
    __syncthreads();

    // --- adjacency bitmask + c1p + xn ---
    if (tid < Mm) {
        int me = s.nbrs[tid];
        unsigned mrow = 0;
        for (int b = 0; b < Mm; b++) {
            int nb = s.nbrs[b];
            bool adj = false;
            #pragma unroll
            for (int j = 0; j < DEG; j++)
                adj = adj || (s.dstl[tid * DEG + j] == nb) ||
                             (s.dstl[b   * DEG + j] == me);
            if (adj) mrow |= (1u << b);
        }
        s.mask[tid] = mrow;
        s.c1p[tid]  = (float)__popc(mrow) * (1.f / (float)Mm);
        s.xnl[tid]  = g_xn[me];
    }
    __syncthreads();

    // --- ownership (warp-aligned) ---
    bool upd;
    int k, m;
    if (tid < 256)      { upd = true;  k = 2 * w + (lane >> 4); m = (lane & 15) + 1; }
    else if (tid < 272) { upd = true;  k = tid - 256;           m = 0; }
    else                { upd = false; k = 0;                   m = 0; }
    const int tbase = k * PT;
    float* Trow = &s.T[m * TSTR + tbase];
    unsigned msk_m = upd ? s.mask[m] : 0u;
    unsigned extras = msk_m & ~1u;          // bit 0 handled explicitly (always set for m>=1)
    const bool ccOwner = upd && (m >= 1) && (m <= MTt);  // computes cc[k][m-1]

    ull ltp[5], McBp[5];
    if (upd) {
        float xn = s.xnl[m];
        float cpv = cA2 * s.c1p[m];
        const float* Grow = g_G + (size_t)s.nbrs[m] * KT + k * MTt;
        const float* f2p  = g_f2n + k * MTt;
        #pragma unroll
        for (int j = 0; j < 5; j++) {
            float a = coefM * (xn + f2p[2*j]   - 2.f * Grow[2*j])   + cpv;
            float b = coefM * (xn + f2p[2*j+1] - 2.f * Grow[2*j+1]) + cpv;
            McBp[j] = pk2(a, b);
            ltp[j] = 0ULL;
        }
    }
    __syncthreads();

    ull ccp[5], y2p[5];
    #pragma unroll
    for (int j = 0; j < 5; j++) { ccp[j] = 0ULL; y2p[j] = 0ULL; }

    for (int it = 0; it < NITER; it++) {
        // A) deferred lt update + softmax -> T row
        if (upd) {
            if (it > 0) {
                #pragma unroll
                for (int j = 0; j < 5; j++) {
                    ull d = fma2r(cA2p, ccp[j], McBp[j]);
                    d = fma2r(ncA4p, y2p[j], d);
                    ltp[j] = fma2r(d, neg1p, ltp[j]);
                }
            }
            float e[10];
            #pragma unroll
            for (int j = 0; j < 5; j++) upk2(e[2*j], e[2*j+1], ltp[j]);
            float mx = e[0];
            #pragma unroll
            for (int t = 1; t < MTt; t++) mx = fmaxf(mx, e[t]);
            float ssum = 0.f;
            #pragma unroll
            for (int t = 0; t < MTt; t++) { e[t] = __expf(e[t] - mx); ssum += e[t]; }
            float inv = (1.f / (float)Mm) / ssum;
            *(float4*)(Trow)     = make_float4(e[0]*inv, e[1]*inv, e[2]*inv, e[3]*inv);
            *(float4*)(Trow + 4) = make_float4(e[4]*inv, e[5]*inv, e[6]*inv, e[7]*inv);
            *(float4*)(Trow + 8) = make_float4(e[8]*inv, e[9]*inv, 0.f, 0.f);
        }
        __syncthreads();

        // B) scalar q (threads 0..159, one column each) || gather y1 (m>=1)
        if (tid < KT) {
            int kk = tid / MTt, cs = tid - kk * MTt;
            int cp = kk * PT + cs;
            float acc = 0.f;
            #pragma unroll
            for (int mm = 0; mm < Mm; mm++) acc += s.T[mm * TSTR + cp];
            s.q[cp] = acc;
        }
        ull y1p[5];
        if (upd && m != 0) {
            // bit 0 always set: start from T[0] chunk (broadcast load)
            const float* t0 = &s.T[tbase];
            float4 v0 = *(const float4*)(t0);
            float4 v1 = *(const float4*)(t0 + 4);
            float4 v2 = *(const float4*)(t0 + 8);
            y1p[0] = pk2(v0.x, v0.y); y1p[1] = pk2(v0.z, v0.w);
            y1p[2] = pk2(v1.x, v1.y); y1p[3] = pk2(v1.z, v1.w);
            y1p[4] = pk2(v2.x, v2.y);
            unsigned msk = extras;            // rare
            while (msk) {
                int b = __ffs(msk) - 1;
                msk &= msk - 1;
                const float* tr = &s.T[b * TSTR + tbase];
                float4 u0 = *(const float4*)(tr);
                float4 u1 = *(const float4*)(tr + 4);
                float4 u2 = *(const float4*)(tr + 8);
                add2(y1p[0], pk2(u0.x, u0.y));
                add2(y1p[1], pk2(u0.z, u0.w));
                add2(y1p[2], pk2(u1.x, u1.y));
                add2(y1p[3], pk2(u1.z, u1.w));
                add2(y1p[4], pk2(u2.x, u2.y));
            }
        }
        __syncthreads();

        // C) cc (owner lanes m=1..10) || row-0 y1 from q || y2 dots (all owners)
        if (ccOwner) {
            int ss = m - 1;
            const float* qp = &s.q[tbase];
            const float* sq = &s.C2sq[(k * MTt + ss) * PT];
            float4 q0 = *(const float4*)(qp), q1 = *(const float4*)(qp + 4),
                   q2 = *(const float4*)(qp + 8);
            float4 s0 = *(const float4*)(sq), s1 = *(const float4*)(sq + 4),
                   s2 = *(const float4*)(sq + 8);
            ull acc = 0ULL;
            ffma2(acc, pk2(q0.x, q0.y), pk2(s0.x, s0.y));
            ffma2(acc, pk2(q0.z, q0.w), pk2(s0.z, s0.w));
            ffma2(acc, pk2(q1.x, q1.y), pk2(s1.x, s1.y));
            ffma2(acc, pk2(q1.z, q1.w), pk2(s1.z, s1.w));
            ffma2(acc, pk2(q2.x, q2.y), pk2(s2.x, s2.y));
            s.cc[tbase + ss] = hadd2(acc);
        }
        if (upd) {
            if (m == 0) {
                const float* qp = &s.q[tbase];
                float4 q0 = *(const float4*)(qp), q1 = *(const float4*)(qp + 4),
                       q2 = *(const float4*)(qp + 8);
                y1p[0] = pk2(q0.x, q0.y); y1p[1] = pk2(q0.z, q0.w);
                y1p[2] = pk2(q1.x, q1.y); y1p[3] = pk2(q1.z, q1.w);
                y1p[4] = pk2(q2.x, q2.y);
                if (!(msk_m & 1u)) {      // diagonal absent: remove T[0]
                    const float* tr = &s.T[tbase];
                    float4 v0 = *(const float4*)(tr), v1 = *(const float4*)(tr + 4),
                           v2 = *(const float4*)(tr + 8);
                    sub2(y1p[0], pk2(v0.x, v0.y));
                    sub2(y1p[1], pk2(v0.z, v0.w));
                    sub2(y1p[2], pk2(v1.x, v1.y));
                    sub2(y1p[3], pk2(v1.z, v1.w));
                    sub2(y1p[4], pk2(v2.x, v2.y));
                }
            }
            float y[10];
            #pragma unroll
            for (int j = 0; j < 5; j++) upk2(y[2*j], y[2*j+1], y1p[j]);
            #pragma unroll
            for (int j = 0; j < 5; j++) y2p[j] = 0ULL;
            #pragma unroll
            for (int t = 0; t < MTt; t++) {
                const float* cr = &s.C2[(k * MTt + t) * PT];
                float4 r0 = *(const float4*)(cr), r1 = *(const float4*)(cr + 4),
                       r2 = *(const float4*)(cr + 8);
                ull yt = pk2(y[t], y[t]);
                ffma2(y2p[0], yt, pk2(r0.x, r0.y));
                ffma2(y2p[1], yt, pk2(r0.z, r0.w));
                ffma2(y2p[2], yt, pk2(r1.x, r1.y));
                ffma2(y2p[3], yt, pk2(r1.z, r1.w));
                ffma2(y2p[4], yt, pk2(r2.x, r2.y));
            }
        }
        __syncthreads();

        // D) read cc chunk (broadcast within k-groups) for the deferred update
        if (upd) {
            const float* cp = &s.cc[tbase];
            float4 c0 = *(const float4*)(cp), c1 = *(const float4*)(cp + 4),
                   c2v = *(const float4*)(cp + 8);
            ccp[0] = pk2(c0.x, c0.y); ccp[1] = pk2(c0.z, c0.w);
            ccp[2] = pk2(c1.x, c1.y); ccp[3] = pk2(c1.z, c1.w);
            ccp[4] = pk2(c2v.x, c2v.y);
        }
    }

    // --- final lt update + softmax -> T, then output marginals ---
    if (upd) {
        #pragma unroll
        for (int j = 0; j < 5; j++) {
            ull d = fma2r(cA2p, ccp[j], McBp[j]);
            d = fma2r(ncA4p, y2p[j], d);
            ltp[j] = fma2r(d, neg1p, ltp[j]);
        }
        float e[10];
        #pragma unroll
        for (int j = 0; j < 5; j++) upk2(e[2*j], e[2*j+1], ltp[j]);
        float mx = e[0];
        #pragma unroll
        for (int t = 1; t < MTt; t++) mx = fmaxf(mx, e[t]);
        float ssum = 0.f;
        #pragma unroll
        for (int t = 0; t < MTt; t++) { e[t] = __expf(e[t] - mx); ssum += e[t]; }
        float inv = (1.f / (float)Mm) / ssum;
        *(float4*)(Trow)     = make_float4(e[0]*inv, e[1]*inv, e[2]*inv, e[3]*inv);
        *(float4*)(Trow + 4) = make_float4(e[4]*inv, e[5]*inv, e[6]*inv, e[7]*inv);
        *(float4*)(Trow + 8) = make_float4(e[8]*inv, e[9]*inv, 0.f, 0.f);
    }
    __syncthreads();
    if (tid < KT) {
        int kk = tid / MTt, cs = tid - kk * MTt;
        int cp = kk * PT + cs;
        float sq = 0.f;
        #pragma unroll
        for (int mm = 0; mm < Mm; mm++) sq += s.T[mm * TSTR + cp];
        out[(size_t)n * KT + tid] = sq;
    }
}

// ---------------------------------------------------------------------------
extern "C" void kernel_launch(void* const* d_in, const int* in_sizes, int n_in,
                              void* d_out, int out_size) {
    const float* x   = (const float*)d_in[0];
    const int*   ei  = (const int*)d_in[1];
    const float* C2g = (const float*)d_in[2];
    const float* F2  = (const float*)d_in[3];
    const float* a0  = (const float*)d_in[4];
    float* out = (float*)d_out;
    const int* dst = ei + Nn * DEG;

    cudaFuncSetAttribute(gemm_kernel, cudaFuncAttributeMaxDynamicSharedMemorySize,
                         GEMM_SMEM);
    cudaFuncSetAttribute(main_kernel, cudaFuncAttributeMaxDynamicSharedMemorySize,
                         (int)sizeof(SmemMain));

    gemm_kernel<<<Nn / GEMM_ROWS, 256, GEMM_SMEM>>>(x, F2);
    main_kernel<<<Nn, THREADS, sizeof(SmemMain)>>>(dst, C2g, a0, out);
}